// round 8
// baseline (speedup 1.0000x reference)
#include <cuda_runtime.h>
#include <math.h>

// Problem constants
#define NB 128      // batch
#define HD 512      // hidden
#define LS 512      // source length
#define TT 128      // target length (MAXLEN)
#define SS 64       // num symbols
#define G3 1536     // 3*H

// ---------------- scratch (device globals; no allocation allowed) ----------
__device__ float    g_enc_out[NB * LS * HD];   // [n][l][h]  134 MB
__device__ float    g_hbuf[2][NB * HD];        // ping-pong hidden state
__device__ float    g_embp[SS * G3];           // emb @ dec_Wih^T + dec_bih
__device__ float    g_Q[NB * TT * HD];         // decoder GRU outputs [n][t][h]
__device__ float    g_ctx[NB * TT * HD];       // attention context
__device__ float    g_ff[NB * TT * HD];        // attn_ff output
__device__ unsigned g_bar_e;                   // grid barrier counter (encoder)
__device__ unsigned g_bar_d;                   // grid barrier counter (decoder)

__device__ __forceinline__ float sigf(float v) { return 1.f / (1.f + expf(-v)); }

// Software grid barrier: 128 co-resident CTAs, monotonic counter.
__device__ __forceinline__ void gsync(unsigned* bar, unsigned target) {
    __threadfence();                       // release
    __syncthreads();
    if (threadIdx.x == 0) {
        atomicAdd(bar, 1u);
        volatile unsigned* p = bar;
        while (*p < target) { __nanosleep(32); }
    }
    __syncthreads();
    __threadfence();                       // acquire
}

// ---------------- init kernel ----------------------------------------------
__global__ void init_enc_kernel() {
    int i = blockIdx.x * 256 + threadIdx.x;
    if (i < NB * HD) g_hbuf[0][i] = 0.f;
    if (i == 0) { g_bar_e = 0u; g_bar_d = 0u; }
}

// ---------------- emb_proj: (64,1536) = emb(64,512) @ dec_Wih^T + bih ------
__global__ __launch_bounds__(256) void embproj_kernel(
    const float* __restrict__ emb, const float* __restrict__ Wih,
    const float* __restrict__ bih)
{
    __shared__ float se[HD];
    int s = blockIdx.x;
    for (int k = threadIdx.x; k < HD; k += 256) se[k] = emb[s * HD + k];
    __syncthreads();
    const float4* s4 = (const float4*)se;
    for (int j = threadIdx.x; j < G3; j += 256) {
        float a = bih[j];
        const float4* w4 = (const float4*)(Wih + j * HD);
        for (int k = 0; k < HD / 4; ++k) {
            float4 wv = w4[k];
            float4 sv = s4[k];
            a = fmaf(sv.x, wv.x, a);
            a = fmaf(sv.y, wv.y, a);
            a = fmaf(sv.z, wv.z, a);
            a = fmaf(sv.w, wv.w, a);
        }
        g_embp[s * G3 + j] = a;
    }
}

// ============================================================================
// Recurrent kernels: 128 CTAs x 256 thr. CTA owns j-tile of 4 (j0=bid*4),
// FULL K=512 (no split-K, no partials). Weights sW[512][12] k-major in smem,
// loaded once. h staged double-buffered in 32 chunks of 16 k (sH padded 132).
// Thread: tx=j (0..3), tyn=tid>>2 -> 2 n rows; acc[3][2] in registers; gate
// computed in registers. Ping-pong g_hbuf => ONE grid barrier per step.
// smem = 24KB + 16.5KB = 40.5KB (static), 1 CTA/SM.
// ============================================================================

// ---------------- encoder persistent kernel --------------------------------
__global__ __launch_bounds__(256) void enc_kernel(
    const float* __restrict__ x, const float* __restrict__ Wih,
    const float* __restrict__ Whh, const float* __restrict__ bih,
    const float* __restrict__ bhh)
{
    __shared__ float sW[512][12];       // [k][g*4 + jj]
    __shared__ float sH[2][16][132];    // [buf][k_local][n] (padded)

    const int tid = threadIdx.x;
    const int bid = blockIdx.x;
    const int j0 = bid * 4;
    const int tx = tid & 3;              // j within tile
    const int tyn = tid >> 2;            // 0..63 -> n = tyn*2
    const int j = j0 + tx;
    const int sn = tid >> 2;             // staging row (0..63)
    const int q = tid & 3;               // staging k-quad

    // Load weight slice ONCE, k-major (12 jrows x 512 k).
#pragma unroll
    for (int it = 0; it < 6; ++it) {
        int idx = tid + it * 256;            // 0..1535
        int jr = idx % 12;                   // g*4 + jj
        int kq = (idx / 12) * 4;             // 0..508
        int g = jr >> 2, jj = jr & 3;
        float4 w = *(const float4*)(Whh + (g * HD + j0 + jj) * HD + kq);
        sW[kq + 0][jr] = w.x;
        sW[kq + 1][jr] = w.y;
        sW[kq + 2][jr] = w.z;
        sW[kq + 3][jr] = w.w;
    }

    // Per-thread gate constants for fixed j.
    const float wr0 = Wih[j * 2],            wr1 = Wih[j * 2 + 1];
    const float wz0 = Wih[(HD + j) * 2],     wz1 = Wih[(HD + j) * 2 + 1];
    const float wn0 = Wih[(2 * HD + j) * 2], wn1 = Wih[(2 * HD + j) * 2 + 1];
    const float bir = bih[j], biz = bih[HD + j], bin_ = bih[2 * HD + j];
    const float bhr = bhh[j], bhz = bhh[HD + j], bhn = bhh[2 * HD + j];

    unsigned bt = 0;
    for (int t = 0; t < LS; ++t) {
        const float* rb = g_hbuf[t & 1];
        float*       wb = g_hbuf[(t + 1) & 1];

        float acc0a = 0.f, acc0b = 0.f;
        float acc1a = 0.f, acc1b = 0.f;
        float acc2a = 0.f, acc2b = 0.f;

        // stage chunk 0 (rows sn and sn+64, k-quad q)
        {
            float4 a = __ldcg((const float4*)(rb + sn * HD + q * 4));
            float4 b = __ldcg((const float4*)(rb + (sn + 64) * HD + q * 4));
            sH[0][q * 4 + 0][sn] = a.x; sH[0][q * 4 + 1][sn] = a.y;
            sH[0][q * 4 + 2][sn] = a.z; sH[0][q * 4 + 3][sn] = a.w;
            sH[0][q * 4 + 0][sn + 64] = b.x; sH[0][q * 4 + 1][sn + 64] = b.y;
            sH[0][q * 4 + 2][sn + 64] = b.z; sH[0][q * 4 + 3][sn + 64] = b.w;
        }
        __syncthreads();

        for (int c = 0; c < 32; ++c) {
            int buf = c & 1;
            float4 na, nb;
            if (c < 31) {
                na = __ldcg((const float4*)(rb + sn * HD + (c + 1) * 16 + q * 4));
                nb = __ldcg((const float4*)(rb + (sn + 64) * HD + (c + 1) * 16 + q * 4));
            }
#pragma unroll
            for (int k = 0; k < 16; ++k) {
                float2 h2 = *(const float2*)&sH[buf][k][tyn * 2];
                const float* wrow = &sW[c * 16 + k][0];
                float w0 = wrow[tx];
                float w1 = wrow[4 + tx];
                float w2 = wrow[8 + tx];
                acc0a = fmaf(h2.x, w0, acc0a); acc0b = fmaf(h2.y, w0, acc0b);
                acc1a = fmaf(h2.x, w1, acc1a); acc1b = fmaf(h2.y, w1, acc1b);
                acc2a = fmaf(h2.x, w2, acc2a); acc2b = fmaf(h2.y, w2, acc2b);
            }
            if (c < 31) {
                int nbuf = 1 - buf;
                sH[nbuf][q * 4 + 0][sn] = na.x; sH[nbuf][q * 4 + 1][sn] = na.y;
                sH[nbuf][q * 4 + 2][sn] = na.z; sH[nbuf][q * 4 + 3][sn] = na.w;
                sH[nbuf][q * 4 + 0][sn + 64] = nb.x; sH[nbuf][q * 4 + 1][sn + 64] = nb.y;
                sH[nbuf][q * 4 + 2][sn + 64] = nb.z; sH[nbuf][q * 4 + 3][sn + 64] = nb.w;
            }
            __syncthreads();
        }

        // gate in registers for (n, n+1) x j
#pragma unroll
        for (int i = 0; i < 2; ++i) {
            int n = tyn * 2 + i;
            float a0 = i ? acc0b : acc0a;
            float a1 = i ? acc1b : acc1a;
            float a2 = i ? acc2b : acc2a;
            float x0 = x[(n * 2 + 0) * LS + t];
            float x1 = x[(n * 2 + 1) * LS + t];
            float r = sigf(fmaf(x1, wr1, fmaf(x0, wr0, bir)) + a0 + bhr);
            float z = sigf(fmaf(x1, wz1, fmaf(x0, wz0, biz)) + a1 + bhz);
            float nn = tanhf(fmaf(x1, wn1, fmaf(x0, wn0, bin_)) + r * (a2 + bhn));
            float hold = __ldcg(rb + n * HD + j);
            float hnew = (1.f - z) * nn + z * hold;
            wb[n * HD + j] = hnew;
            g_enc_out[(n * LS + t) * HD + j] = hnew;
        }
        bt += 128; gsync(&g_bar_e, bt);
    }
}

// ---------------- decoder persistent kernel --------------------------------
__global__ __launch_bounds__(256) void dec_kernel(
    const int* __restrict__ target, const float* __restrict__ Whh,
    const float* __restrict__ bhh, float* __restrict__ hN)
{
    __shared__ float sW[512][12];
    __shared__ float sH[2][16][132];

    const int tid = threadIdx.x;
    const int bid = blockIdx.x;
    const int j0 = bid * 4;
    const int tx = tid & 3;
    const int tyn = tid >> 2;
    const int j = j0 + tx;
    const int sn = tid >> 2;
    const int q = tid & 3;

#pragma unroll
    for (int it = 0; it < 6; ++it) {
        int idx = tid + it * 256;
        int jr = idx % 12;
        int kq = (idx / 12) * 4;
        int g = jr >> 2, jj = jr & 3;
        float4 w = *(const float4*)(Whh + (g * HD + j0 + jj) * HD + kq);
        sW[kq + 0][jr] = w.x;
        sW[kq + 1][jr] = w.y;
        sW[kq + 2][jr] = w.z;
        sW[kq + 3][jr] = w.w;
    }

    const float bhr = bhh[j], bhz = bhh[HD + j], bhn = bhh[2 * HD + j];

    unsigned bt = 0;
    for (int t = 0; t < TT; ++t) {
        const float* rb = g_hbuf[t & 1];
        float*       wb = g_hbuf[(t + 1) & 1];

        float acc0a = 0.f, acc0b = 0.f;
        float acc1a = 0.f, acc1b = 0.f;
        float acc2a = 0.f, acc2b = 0.f;

        {
            float4 a = __ldcg((const float4*)(rb + sn * HD + q * 4));
            float4 b = __ldcg((const float4*)(rb + (sn + 64) * HD + q * 4));
            sH[0][q * 4 + 0][sn] = a.x; sH[0][q * 4 + 1][sn] = a.y;
            sH[0][q * 4 + 2][sn] = a.z; sH[0][q * 4 + 3][sn] = a.w;
            sH[0][q * 4 + 0][sn + 64] = b.x; sH[0][q * 4 + 1][sn + 64] = b.y;
            sH[0][q * 4 + 2][sn + 64] = b.z; sH[0][q * 4 + 3][sn + 64] = b.w;
        }
        __syncthreads();

        for (int c = 0; c < 32; ++c) {
            int buf = c & 1;
            float4 na, nb;
            if (c < 31) {
                na = __ldcg((const float4*)(rb + sn * HD + (c + 1) * 16 + q * 4));
                nb = __ldcg((const float4*)(rb + (sn + 64) * HD + (c + 1) * 16 + q * 4));
            }
#pragma unroll
            for (int k = 0; k < 16; ++k) {
                float2 h2 = *(const float2*)&sH[buf][k][tyn * 2];
                const float* wrow = &sW[c * 16 + k][0];
                float w0 = wrow[tx];
                float w1 = wrow[4 + tx];
                float w2 = wrow[8 + tx];
                acc0a = fmaf(h2.x, w0, acc0a); acc0b = fmaf(h2.y, w0, acc0b);
                acc1a = fmaf(h2.x, w1, acc1a); acc1b = fmaf(h2.y, w1, acc1b);
                acc2a = fmaf(h2.x, w2, acc2a); acc2b = fmaf(h2.y, w2, acc2b);
            }
            if (c < 31) {
                int nbuf = 1 - buf;
                sH[nbuf][q * 4 + 0][sn] = na.x; sH[nbuf][q * 4 + 1][sn] = na.y;
                sH[nbuf][q * 4 + 2][sn] = na.z; sH[nbuf][q * 4 + 3][sn] = na.w;
                sH[nbuf][q * 4 + 0][sn + 64] = nb.x; sH[nbuf][q * 4 + 1][sn + 64] = nb.y;
                sH[nbuf][q * 4 + 2][sn + 64] = nb.z; sH[nbuf][q * 4 + 3][sn + 64] = nb.w;
            }
            __syncthreads();
        }

#pragma unroll
        for (int i = 0; i < 2; ++i) {
            int n = tyn * 2 + i;
            float a0 = i ? acc0b : acc0a;
            float a1 = i ? acc1b : acc1a;
            float a2 = i ? acc2b : acc2a;
            int tok = (t == 0) ? 0 : target[n * TT + t - 1];
            const float* ep = g_embp + tok * G3;
            float gir = ep[j], giz = ep[HD + j], gin = ep[2 * HD + j];
            float r = sigf(gir + a0 + bhr);
            float z = sigf(giz + a1 + bhz);
            float nn = tanhf(gin + r * (a2 + bhn));
            float hold = __ldcg(rb + n * HD + j);
            float hnew = (1.f - z) * nn + z * hold;
            wb[n * HD + j] = hnew;
            g_Q[(n * TT + t) * HD + j] = hnew;
            if (t == TT - 1) hN[n * HD + j] = hnew;
        }
        bt += 128; gsync(&g_bar_d, bt);
    }
}

// ---------------- scores: S[n][i][l] = sum_h Q[n][i][h]*E[n][l][h] ---------
__global__ __launch_bounds__(256) void scores_kernel(float* __restrict__ outw)
{
    __shared__ float sq[64][36], se[64][36];
    int bid = blockIdx.x;
    int n = bid >> 4;
    int rr = bid & 15;
    int i0 = (rr >> 3) * 64, l0 = (rr & 7) * 64;
    int tid = threadIdx.x, tx = tid & 15, ty = tid >> 4;
    float acc[4][4];
#pragma unroll
    for (int i = 0; i < 4; i++)
#pragma unroll
        for (int l = 0; l < 4; l++) acc[i][l] = 0.f;

    for (int st = 0; st < 16; ++st) {
        int k0 = st * 32;
        for (int v = tid; v < 512; v += 256) {
            int r = v >> 3, c = (v & 7) * 4;
            *(float4*)&sq[r][c] =
                *(const float4*)(g_Q + (n * TT + i0 + r) * HD + k0 + c);
            *(float4*)&se[r][c] =
                *(const float4*)(g_enc_out + (n * LS + l0 + r) * HD + k0 + c);
        }
        __syncthreads();
#pragma unroll
        for (int k = 0; k < 32; ++k) {
            float qv[4], ev[4];
#pragma unroll
            for (int i = 0; i < 4; i++) qv[i] = sq[ty * 4 + i][k];
#pragma unroll
            for (int l = 0; l < 4; l++) ev[l] = se[tx * 4 + l][k];
#pragma unroll
            for (int i = 0; i < 4; i++)
#pragma unroll
                for (int l = 0; l < 4; l++)
                    acc[i][l] = fmaf(qv[i], ev[l], acc[i][l]);
        }
        __syncthreads();
    }
#pragma unroll
    for (int i = 0; i < 4; i++)
#pragma unroll
        for (int l = 0; l < 4; l++)
            outw[(size_t)(n * TT + i0 + ty * 4 + i) * LS + l0 + tx * 4 + l] = acc[i][l];
}

// ---------------- softmax over l (in-place in all_w region) ----------------
__global__ void softmax_kernel(float* __restrict__ w)
{
    int row = blockIdx.x * 8 + (threadIdx.x >> 5);
    int lane = threadIdx.x & 31;
    float* p = w + (size_t)row * LS;
    float v[16];
    float m = -1e30f;
#pragma unroll
    for (int u = 0; u < 16; ++u) { v[u] = p[lane + u * 32]; m = fmaxf(m, v[u]); }
#pragma unroll
    for (int o = 16; o; o >>= 1) m = fmaxf(m, __shfl_xor_sync(0xffffffffu, m, o));
    float s = 0.f;
#pragma unroll
    for (int u = 0; u < 16; ++u) { v[u] = expf(v[u] - m); s += v[u]; }
#pragma unroll
    for (int o = 16; o; o >>= 1) s += __shfl_xor_sync(0xffffffffu, s, o);
    float inv = 1.f / s;
#pragma unroll
    for (int u = 0; u < 16; ++u) p[lane + u * 32] = v[u] * inv;
}

// ---------------- context: C[n][i][h] = sum_l w[n][i][l]*E[n][l][h] --------
__global__ __launch_bounds__(256) void ctx_kernel(const float* __restrict__ w)
{
    __shared__ float swt[64][36];   // [i][l-chunk]
    __shared__ float se[32][68];    // [l-chunk][h]
    int bid = blockIdx.x;
    int n = bid >> 4;
    int rr = bid & 15;
    int i0 = (rr >> 3) * 64, h0 = (rr & 7) * 64;
    int tid = threadIdx.x, tx = tid & 15, ty = tid >> 4;
    float acc[4][4];
#pragma unroll
    for (int i = 0; i < 4; i++)
#pragma unroll
        for (int h = 0; h < 4; h++) acc[i][h] = 0.f;

    for (int st = 0; st < 16; ++st) {
        int l0 = st * 32;
        for (int v = tid; v < 512; v += 256) {
            int r = v >> 3, c = (v & 7) * 4;
            *(float4*)&swt[r][c] =
                *(const float4*)(w + (size_t)(n * TT + i0 + r) * LS + l0 + c);
        }
        for (int v = tid; v < 512; v += 256) {
            int r = v >> 4, c = (v & 15) * 4;
            *(float4*)&se[r][c] =
                *(const float4*)(g_enc_out + (n * LS + l0 + r) * HD + h0 + c);
        }
        __syncthreads();
#pragma unroll
        for (int k = 0; k < 32; ++k) {
            float wv[4], ev[4];
#pragma unroll
            for (int i = 0; i < 4; i++) wv[i] = swt[ty * 4 + i][k];
#pragma unroll
            for (int h = 0; h < 4; h++) ev[h] = se[k][tx * 4 + h];
#pragma unroll
            for (int i = 0; i < 4; i++)
#pragma unroll
                for (int h = 0; h < 4; h++)
                    acc[i][h] = fmaf(wv[i], ev[h], acc[i][h]);
        }
        __syncthreads();
    }
#pragma unroll
    for (int i = 0; i < 4; i++)
#pragma unroll
        for (int h = 0; h < 4; h++)
            g_ctx[(n * TT + i0 + ty * 4 + i) * HD + h0 + tx * 4 + h] = acc[i][h];
}

// ---------------- ff: g_ff[m][o] = [Q|ctx][m][:] . attn_ff_W[o][:] + b[o] --
__global__ __launch_bounds__(256) void ff_kernel(
    const float* __restrict__ W, const float* __restrict__ b)
{
    __shared__ float sa[32][132];   // [k][m] + pad
    __shared__ float sw[32][68];    // [k][o] + pad
    int bid = blockIdx.x;
    int m0 = (bid >> 3) * 128, o0 = (bid & 7) * 64;
    int tid = threadIdx.x, tx = tid & 15, ty = tid >> 4;
    float acc[8][4];
#pragma unroll
    for (int i = 0; i < 8; i++)
#pragma unroll
        for (int o = 0; o < 4; o++) acc[i][o] = 0.f;

    for (int st = 0; st < 32; ++st) {
        int k0 = st * 32;
        const float* A = (k0 < HD) ? g_Q : g_ctx;
        int koff = (k0 < HD) ? k0 : k0 - HD;
#pragma unroll
        for (int it = 0; it < 4; ++it) {
            int idx = tid + it * 256;           // 0..1023
            int m = idx & 127, kq = (idx >> 7) * 4;
            float4 a = *(const float4*)(A + (m0 + m) * HD + koff + kq);
            sa[kq + 0][m] = a.x; sa[kq + 1][m] = a.y;
            sa[kq + 2][m] = a.z; sa[kq + 3][m] = a.w;
        }
#pragma unroll
        for (int it = 0; it < 2; ++it) {
            int idx = tid + it * 256;           // 0..511
            int o = idx & 63, kq = (idx >> 6) * 4;
            float4 wv = *(const float4*)(W + (o0 + o) * (2 * HD) + k0 + kq);
            sw[kq + 0][o] = wv.x; sw[kq + 1][o] = wv.y;
            sw[kq + 2][o] = wv.z; sw[kq + 3][o] = wv.w;
        }
        __syncthreads();
#pragma unroll
        for (int k = 0; k < 32; ++k) {
            float4 a0 = *(const float4*)&sa[k][ty * 8];
            float4 a1 = *(const float4*)&sa[k][ty * 8 + 4];
            float4 wv = *(const float4*)&sw[k][tx * 4];
            float am[8] = {a0.x, a0.y, a0.z, a0.w, a1.x, a1.y, a1.z, a1.w};
            float wm[4] = {wv.x, wv.y, wv.z, wv.w};
#pragma unroll
            for (int i = 0; i < 8; i++)
#pragma unroll
                for (int o = 0; o < 4; o++)
                    acc[i][o] = fmaf(am[i], wm[o], acc[i][o]);
        }
        __syncthreads();
    }
    float4 bb = *(const float4*)(b + o0 + tx * 4);
#pragma unroll
    for (int i = 0; i < 8; i++) {
        float4 r = make_float4(acc[i][0] + bb.x, acc[i][1] + bb.y,
                               acc[i][2] + bb.z, acc[i][3] + bb.w);
        *(float4*)(g_ff + (m0 + ty * 8 + i) * HD + o0 + tx * 4) = r;
    }
}

// ---------------- fc: v_out[m][s] = ff[m][:] . fc_W[s][:] + fc_b[s] --------
__global__ __launch_bounds__(256) void fc_kernel(
    const float* __restrict__ W, const float* __restrict__ b,
    float* __restrict__ vout)
{
    __shared__ float sa[128][36], swt[64][36];
    int m0 = blockIdx.x * 128;
    int tid = threadIdx.x, tx = tid & 15, ty = tid >> 4;
    float acc[8][4];
#pragma unroll
    for (int i = 0; i < 8; i++)
#pragma unroll
        for (int s = 0; s < 4; s++) acc[i][s] = 0.f;

    for (int st = 0; st < 16; ++st) {
        int k0 = st * 32;
        for (int v = tid; v < 1024; v += 256) {
            int r = v >> 3, c = (v & 7) * 4;
            *(float4*)&sa[r][c] = *(const float4*)(g_ff + (m0 + r) * HD + k0 + c);
        }
        for (int v = tid; v < 512; v += 256) {
            int r = v >> 3, c = (v & 7) * 4;
            *(float4*)&swt[r][c] = *(const float4*)(W + r * HD + k0 + c);
        }
        __syncthreads();
#pragma unroll
        for (int k = 0; k < 32; ++k) {
            float av[8], wv[4];
#pragma unroll
            for (int i = 0; i < 8; i++) av[i] = sa[ty * 8 + i][k];
#pragma unroll
            for (int s = 0; s < 4; s++) wv[s] = swt[tx * 4 + s][k];
#pragma unroll
            for (int i = 0; i < 8; i++)
#pragma unroll
                for (int s = 0; s < 4; s++)
                    acc[i][s] = fmaf(av[i], wv[s], acc[i][s]);
        }
        __syncthreads();
    }
#pragma unroll
    for (int i = 0; i < 8; i++)
#pragma unroll
        for (int s = 0; s < 4; s++)
            vout[(m0 + ty * 8 + i) * SS + tx * 4 + s] = acc[i][s] + b[tx * 4 + s];
}

// ---------------- launch ----------------------------------------------------
extern "C" void kernel_launch(void* const* d_in, const int* in_sizes, int n_in,
                              void* d_out, int out_size)
{
    const float* x      = (const float*)d_in[0];
    const int*   target = (const int*)  d_in[1];
    const float* eWih   = (const float*)d_in[2];
    const float* eWhh   = (const float*)d_in[3];
    const float* ebih   = (const float*)d_in[4];
    const float* ebhh   = (const float*)d_in[5];
    const float* dWih   = (const float*)d_in[6];
    const float* dWhh   = (const float*)d_in[7];
    const float* dbih   = (const float*)d_in[8];
    const float* dbhh   = (const float*)d_in[9];
    const float* emb    = (const float*)d_in[10];
    const float* aW     = (const float*)d_in[11];
    const float* ab     = (const float*)d_in[12];
    const float* fW     = (const float*)d_in[13];
    const float* fb     = (const float*)d_in[14];

    float* out   = (float*)d_out;
    float* v_out = out;                       // (128,128,64)  = 1048576
    float* hN    = out + 1048576;             // (1,128,512)   = 65536
    float* allw  = out + 1048576 + 65536;     // (128,128,512) = 8388608

    init_enc_kernel<<<256, 256>>>();
    embproj_kernel<<<64, 256>>>(emb, dWih, dbih);
    enc_kernel<<<128, 256>>>(x, eWih, eWhh, ebih, ebhh);
    dec_kernel<<<128, 256>>>(target, dWhh, dbhh, hN);
    scores_kernel<<<2048, 256>>>(allw);
    softmax_kernel<<<2048, 256>>>(allw);
    ctx_kernel<<<2048, 256>>>(allw);
    ff_kernel<<<1024, 256>>>(aW, ab);
    fc_kernel<<<128, 256>>>(fW, fb, v_out);
}

// round 9
// speedup vs baseline: 1.4751x; 1.4751x over previous
#include <cuda_runtime.h>
#include <math.h>

// Problem constants
#define NB 128      // batch
#define HD 512      // hidden
#define LS 512      // source length
#define TT 128      // target length (MAXLEN)
#define SS 64       // num symbols
#define G3 1536     // 3*H

// ---------------- scratch (device globals; no allocation allowed) ----------
__device__ float    g_enc_out[NB * LS * HD];   // [n][l][h]  134 MB
__device__ float    g_h[NB * HD];              // current hidden state
__device__ float    g_ghp[8 * NB * G3];        // split-K partials (8 slices)
__device__ float    g_embp[SS * G3];           // emb @ dec_Wih^T + dec_bih
__device__ float    g_Q[NB * TT * HD];         // decoder GRU outputs [n][t][h]
__device__ float    g_ctx[NB * TT * HD];       // attention context
__device__ float    g_ff[NB * TT * HD];        // attn_ff output
// Hierarchical barrier: 8 counters per phase, strided 64 words (256 B) so
// arrivals land on different LTS slices. [0..511] = encoder, [512..1023] = dec.
__device__ unsigned g_barc[1024];

__device__ __forceinline__ float sigf(float v) { return 1.f / (1.f + expf(-v)); }

// Spread grid barrier: CTA (bid&7) arrives on counter (bid&7); 16 arrivals per
// counter per barrier (serialized per-address, parallel across 8 slices).
// Lanes 0..7 poll one counter each. target increases by 16 per barrier.
__device__ __forceinline__ void gsync(unsigned* ctr, unsigned target) {
    __threadfence();                        // release
    __syncthreads();
    if (threadIdx.x == 0)
        atomicAdd(ctr + (blockIdx.x & 7) * 64, 1u);
    if (threadIdx.x < 8) {
        volatile unsigned* p = ctr + threadIdx.x * 64;
        while (*p < target) { }
    }
    __syncthreads();
    __threadfence();                        // acquire
}

// ---------------- init kernel ----------------------------------------------
__global__ void init_enc_kernel() {
    int i = blockIdx.x * 256 + threadIdx.x;
    if (i < NB * HD) g_h[i] = 0.f;
    if (i < 1024) g_barc[i] = 0u;
}

// ---------------- emb_proj: (64,1536) = emb(64,512) @ dec_Wih^T + bih ------
__global__ __launch_bounds__(256) void embproj_kernel(
    const float* __restrict__ emb, const float* __restrict__ Wih,
    const float* __restrict__ bih)
{
    __shared__ float se[HD];
    int s = blockIdx.x;
    for (int k = threadIdx.x; k < HD; k += 256) se[k] = emb[s * HD + k];
    __syncthreads();
    const float4* s4 = (const float4*)se;
    for (int j = threadIdx.x; j < G3; j += 256) {
        float a = bih[j];
        const float4* w4 = (const float4*)(Wih + j * HD);
        for (int k = 0; k < HD / 4; ++k) {
            float4 wv = w4[k];
            float4 sv = s4[k];
            a = fmaf(sv.x, wv.x, a);
            a = fmaf(sv.y, wv.y, a);
            a = fmaf(sv.z, wv.z, a);
            a = fmaf(sv.w, wv.w, a);
        }
        g_embp[s * G3 + j] = a;
    }
}

// ============================================================================
// Recurrent kernels. 128 CTAs = ks(8 k-slices of 64) x jb(16 j-tiles of 32).
// CTA computes partial gh for all 128 n rows, 96 jrows (3g x 32j), its 64-wide
// k slice. Weights k-major in static smem, loaded ONCE. h staged (2 x 32k)
// k-major. Thread tile: 8n x (3g x 2j). smem = 24KB + 16KB = 40KB.
// ============================================================================

// ---------------- encoder persistent kernel --------------------------------
__global__ __launch_bounds__(256) void enc_kernel(
    const float* __restrict__ x, const float* __restrict__ Wih,
    const float* __restrict__ Whh, const float* __restrict__ bih,
    const float* __restrict__ bhh)
{
    __shared__ float sW[64][96];    // [k_local][g*32+jj]
    __shared__ float sH[32][128];   // [k_local][n]

    const int tid = threadIdx.x;
    const int bid = blockIdx.x;
    const int ks = bid & 7;              // k-slice 0..7 (64 wide)
    const int jb = bid >> 3;             // j tile 0..15 (32 cols)
    const int j0 = jb * 32, kb = ks * 64;
    const int tx = tid & 15, ty = tid >> 4;
    const int nl = ty * 8;               // 8 n rows per thread

    // Load weight slice ONCE, k-major: jrow = g*32+jj (96 rows), k 0..63.
#pragma unroll
    for (int it = 0; it < 6; ++it) {
        int idx = tid + it * 256;            // 0..1535
        int jrow = idx % 96;
        int kc = (idx / 96) * 4;             // 0..60
        int g = jrow >> 5, jj = jrow & 31;
        float4 w = *(const float4*)(Whh + (g * HD + j0 + jj) * HD + kb + kc);
        sW[kc + 0][jrow] = w.x;
        sW[kc + 1][jrow] = w.y;
        sW[kc + 2][jrow] = w.z;
        sW[kc + 3][jrow] = w.w;
    }

    unsigned bt = 0;
    for (int t = 0; t < LS; ++t) {
        float acc[3][8][2];
#pragma unroll
        for (int g = 0; g < 3; g++)
#pragma unroll
            for (int i = 0; i < 8; i++) { acc[g][i][0] = 0.f; acc[g][i][1] = 0.f; }

#pragma unroll
        for (int st = 0; st < 2; ++st) {
            int k0 = kb + st * 32;
            // stage h tile k-major: sH[k][n], n = all 128 rows
#pragma unroll
            for (int it = 0; it < 4; ++it) {
                int idx = tid + it * 256;    // 0..1023
                int n = idx & 127;
                int kc = (idx >> 7) * 4;     // 0..28
                float4 h4 = __ldcg((const float4*)(g_h + n * HD + k0 + kc));
                sH[kc + 0][n] = h4.x;
                sH[kc + 1][n] = h4.y;
                sH[kc + 2][n] = h4.z;
                sH[kc + 3][n] = h4.w;
            }
            __syncthreads();

#pragma unroll 4
            for (int k = 0; k < 32; ++k) {
                float4 ha = *(const float4*)&sH[k][nl];
                float4 hb = *(const float4*)&sH[k][nl + 4];
                float2 w0 = *(const float2*)&sW[st * 32 + k][tx * 2];
                float2 w1 = *(const float2*)&sW[st * 32 + k][32 + tx * 2];
                float2 w2 = *(const float2*)&sW[st * 32 + k][64 + tx * 2];
                float hv[8] = {ha.x, ha.y, ha.z, ha.w, hb.x, hb.y, hb.z, hb.w};
#pragma unroll
                for (int i = 0; i < 8; i++) {
                    acc[0][i][0] = fmaf(hv[i], w0.x, acc[0][i][0]);
                    acc[0][i][1] = fmaf(hv[i], w0.y, acc[0][i][1]);
                    acc[1][i][0] = fmaf(hv[i], w1.x, acc[1][i][0]);
                    acc[1][i][1] = fmaf(hv[i], w1.y, acc[1][i][1]);
                    acc[2][i][0] = fmaf(hv[i], w2.x, acc[2][i][0]);
                    acc[2][i][1] = fmaf(hv[i], w2.y, acc[2][i][1]);
                }
            }
            __syncthreads();
        }

        // store partials (float2)
        const int jl = j0 + tx * 2;
        const int nb = nl;
#pragma unroll
        for (int g = 0; g < 3; g++)
#pragma unroll
            for (int i = 0; i < 8; i++)
                *(float2*)(g_ghp + (ks * NB + nb + i) * G3 + g * HD + jl) =
                    make_float2(acc[g][i][0], acc[g][i][1]);
        bt += 16; gsync(g_barc, bt);

        // gate phase: 65536 (n,j) over 32768 threads
        int Gt = bid * 256 + tid;
#pragma unroll
        for (int e = 0; e < 2; ++e) {
            int idx = Gt + e * 32768;
            int n = idx >> 9, j = idx & 511;
            float x0 = x[(n * 2 + 0) * LS + t];
            float x1 = x[(n * 2 + 1) * LS + t];
            float ghr = bhh[j], ghz = bhh[HD + j], ghn = bhh[2 * HD + j];
#pragma unroll
            for (int q = 0; q < 8; ++q) {
                const float* p = g_ghp + (q * NB + n) * G3 + j;
                ghr += __ldcg(p);
                ghz += __ldcg(p + HD);
                ghn += __ldcg(p + 2 * HD);
            }
            float gir = fmaf(x1, Wih[j * 2 + 1], fmaf(x0, Wih[j * 2], bih[j]));
            float giz = fmaf(x1, Wih[(HD + j) * 2 + 1],
                             fmaf(x0, Wih[(HD + j) * 2], bih[HD + j]));
            float gin = fmaf(x1, Wih[(2 * HD + j) * 2 + 1],
                             fmaf(x0, Wih[(2 * HD + j) * 2], bih[2 * HD + j]));
            float r = sigf(gir + ghr);
            float z = sigf(giz + ghz);
            float nn = tanhf(gin + r * ghn);
            float hold = __ldcg(g_h + n * HD + j);
            float hnew = (1.f - z) * nn + z * hold;
            g_h[n * HD + j] = hnew;
            g_enc_out[(n * LS + t) * HD + j] = hnew;
        }
        bt += 16; gsync(g_barc, bt);
    }
}

// ---------------- decoder persistent kernel --------------------------------
__global__ __launch_bounds__(256) void dec_kernel(
    const int* __restrict__ target, const float* __restrict__ Whh,
    const float* __restrict__ bhh)
{
    __shared__ float sW[64][96];
    __shared__ float sH[32][128];

    const int tid = threadIdx.x;
    const int bid = blockIdx.x;
    const int ks = bid & 7;
    const int jb = bid >> 3;
    const int j0 = jb * 32, kb = ks * 64;
    const int tx = tid & 15, ty = tid >> 4;
    const int nl = ty * 8;

#pragma unroll
    for (int it = 0; it < 6; ++it) {
        int idx = tid + it * 256;
        int jrow = idx % 96;
        int kc = (idx / 96) * 4;
        int g = jrow >> 5, jj = jrow & 31;
        float4 w = *(const float4*)(Whh + (g * HD + j0 + jj) * HD + kb + kc);
        sW[kc + 0][jrow] = w.x;
        sW[kc + 1][jrow] = w.y;
        sW[kc + 2][jrow] = w.z;
        sW[kc + 3][jrow] = w.w;
    }

    unsigned bt = 0;
    for (int t = 0; t < TT; ++t) {
        float acc[3][8][2];
#pragma unroll
        for (int g = 0; g < 3; g++)
#pragma unroll
            for (int i = 0; i < 8; i++) { acc[g][i][0] = 0.f; acc[g][i][1] = 0.f; }

#pragma unroll
        for (int st = 0; st < 2; ++st) {
            int k0 = kb + st * 32;
#pragma unroll
            for (int it = 0; it < 4; ++it) {
                int idx = tid + it * 256;
                int n = idx & 127;
                int kc = (idx >> 7) * 4;
                float4 h4 = __ldcg((const float4*)(g_h + n * HD + k0 + kc));
                sH[kc + 0][n] = h4.x;
                sH[kc + 1][n] = h4.y;
                sH[kc + 2][n] = h4.z;
                sH[kc + 3][n] = h4.w;
            }
            __syncthreads();

#pragma unroll 4
            for (int k = 0; k < 32; ++k) {
                float4 ha = *(const float4*)&sH[k][nl];
                float4 hb = *(const float4*)&sH[k][nl + 4];
                float2 w0 = *(const float2*)&sW[st * 32 + k][tx * 2];
                float2 w1 = *(const float2*)&sW[st * 32 + k][32 + tx * 2];
                float2 w2 = *(const float2*)&sW[st * 32 + k][64 + tx * 2];
                float hv[8] = {ha.x, ha.y, ha.z, ha.w, hb.x, hb.y, hb.z, hb.w};
#pragma unroll
                for (int i = 0; i < 8; i++) {
                    acc[0][i][0] = fmaf(hv[i], w0.x, acc[0][i][0]);
                    acc[0][i][1] = fmaf(hv[i], w0.y, acc[0][i][1]);
                    acc[1][i][0] = fmaf(hv[i], w1.x, acc[1][i][0]);
                    acc[1][i][1] = fmaf(hv[i], w1.y, acc[1][i][1]);
                    acc[2][i][0] = fmaf(hv[i], w2.x, acc[2][i][0]);
                    acc[2][i][1] = fmaf(hv[i], w2.y, acc[2][i][1]);
                }
            }
            __syncthreads();
        }

        const int jl = j0 + tx * 2;
#pragma unroll
        for (int g = 0; g < 3; g++)
#pragma unroll
            for (int i = 0; i < 8; i++)
                *(float2*)(g_ghp + (ks * NB + nl + i) * G3 + g * HD + jl) =
                    make_float2(acc[g][i][0], acc[g][i][1]);
        bt += 16; gsync(g_barc + 512, bt);

        int Gt = bid * 256 + tid;
#pragma unroll
        for (int e = 0; e < 2; ++e) {
            int idx = Gt + e * 32768;
            int n = idx >> 9, j = idx & 511;
            int tok = (t == 0) ? 0 : target[n * TT + t - 1];
            const float* ep = g_embp + tok * G3;
            float gir = ep[j], giz = ep[HD + j], gin = ep[2 * HD + j];
            float ghr = bhh[j], ghz = bhh[HD + j], ghn = bhh[2 * HD + j];
#pragma unroll
            for (int q = 0; q < 8; ++q) {
                const float* p = g_ghp + (q * NB + n) * G3 + j;
                ghr += __ldcg(p);
                ghz += __ldcg(p + HD);
                ghn += __ldcg(p + 2 * HD);
            }
            float r = sigf(gir + ghr);
            float z = sigf(giz + ghz);
            float nn = tanhf(gin + r * ghn);
            float hold = __ldcg(g_h + n * HD + j);
            float hnew = (1.f - z) * nn + z * hold;
            g_h[n * HD + j] = hnew;
            g_Q[(n * TT + t) * HD + j] = hnew;
        }
        bt += 16; gsync(g_barc + 512, bt);
    }
}

// ---------------- dec_hN copy ----------------------------------------------
__global__ void copyh_kernel(float* __restrict__ dst) {
    int i = blockIdx.x * 256 + threadIdx.x;
    dst[i] = g_h[i];
}

// ---------------- scores: S[n][i][l] = sum_h Q[n][i][h]*E[n][l][h] ---------
__global__ __launch_bounds__(256) void scores_kernel(float* __restrict__ outw)
{
    __shared__ float sq[64][36], se[64][36];
    int bid = blockIdx.x;
    int n = bid >> 4;
    int rr = bid & 15;
    int i0 = (rr >> 3) * 64, l0 = (rr & 7) * 64;
    int tid = threadIdx.x, tx = tid & 15, ty = tid >> 4;
    float acc[4][4];
#pragma unroll
    for (int i = 0; i < 4; i++)
#pragma unroll
        for (int l = 0; l < 4; l++) acc[i][l] = 0.f;

    for (int st = 0; st < 16; ++st) {
        int k0 = st * 32;
        for (int v = tid; v < 512; v += 256) {
            int r = v >> 3, c = (v & 7) * 4;
            *(float4*)&sq[r][c] =
                *(const float4*)(g_Q + (n * TT + i0 + r) * HD + k0 + c);
            *(float4*)&se[r][c] =
                *(const float4*)(g_enc_out + (n * LS + l0 + r) * HD + k0 + c);
        }
        __syncthreads();
#pragma unroll
        for (int k = 0; k < 32; ++k) {
            float qv[4], ev[4];
#pragma unroll
            for (int i = 0; i < 4; i++) qv[i] = sq[ty * 4 + i][k];
#pragma unroll
            for (int l = 0; l < 4; l++) ev[l] = se[tx * 4 + l][k];
#pragma unroll
            for (int i = 0; i < 4; i++)
#pragma unroll
                for (int l = 0; l < 4; l++)
                    acc[i][l] = fmaf(qv[i], ev[l], acc[i][l]);
        }
        __syncthreads();
    }
#pragma unroll
    for (int i = 0; i < 4; i++)
#pragma unroll
        for (int l = 0; l < 4; l++)
            outw[(size_t)(n * TT + i0 + ty * 4 + i) * LS + l0 + tx * 4 + l] = acc[i][l];
}

// ---------------- softmax over l (in-place in all_w region) ----------------
__global__ void softmax_kernel(float* __restrict__ w)
{
    int row = blockIdx.x * 8 + (threadIdx.x >> 5);
    int lane = threadIdx.x & 31;
    float* p = w + (size_t)row * LS;
    float v[16];
    float m = -1e30f;
#pragma unroll
    for (int u = 0; u < 16; ++u) { v[u] = p[lane + u * 32]; m = fmaxf(m, v[u]); }
#pragma unroll
    for (int o = 16; o; o >>= 1) m = fmaxf(m, __shfl_xor_sync(0xffffffffu, m, o));
    float s = 0.f;
#pragma unroll
    for (int u = 0; u < 16; ++u) { v[u] = expf(v[u] - m); s += v[u]; }
#pragma unroll
    for (int o = 16; o; o >>= 1) s += __shfl_xor_sync(0xffffffffu, s, o);
    float inv = 1.f / s;
#pragma unroll
    for (int u = 0; u < 16; ++u) p[lane + u * 32] = v[u] * inv;
}

// ---------------- context: C[n][i][h] = sum_l w[n][i][l]*E[n][l][h] --------
__global__ __launch_bounds__(256) void ctx_kernel(const float* __restrict__ w)
{
    __shared__ float swt[64][36];   // [i][l-chunk]
    __shared__ float se[32][68];    // [l-chunk][h]
    int bid = blockIdx.x;
    int n = bid >> 4;
    int rr = bid & 15;
    int i0 = (rr >> 3) * 64, h0 = (rr & 7) * 64;
    int tid = threadIdx.x, tx = tid & 15, ty = tid >> 4;
    float acc[4][4];
#pragma unroll
    for (int i = 0; i < 4; i++)
#pragma unroll
        for (int h = 0; h < 4; h++) acc[i][h] = 0.f;

    for (int st = 0; st < 16; ++st) {
        int l0 = st * 32;
        for (int v = tid; v < 512; v += 256) {
            int r = v >> 3, c = (v & 7) * 4;
            *(float4*)&swt[r][c] =
                *(const float4*)(w + (size_t)(n * TT + i0 + r) * LS + l0 + c);
        }
        for (int v = tid; v < 512; v += 256) {
            int r = v >> 4, c = (v & 15) * 4;
            *(float4*)&se[r][c] =
                *(const float4*)(g_enc_out + (n * LS + l0 + r) * HD + h0 + c);
        }
        __syncthreads();
#pragma unroll
        for (int k = 0; k < 32; ++k) {
            float wv[4], ev[4];
#pragma unroll
            for (int i = 0; i < 4; i++) wv[i] = swt[ty * 4 + i][k];
#pragma unroll
            for (int h = 0; h < 4; h++) ev[h] = se[k][tx * 4 + h];
#pragma unroll
            for (int i = 0; i < 4; i++)
#pragma unroll
                for (int h = 0; h < 4; h++)
                    acc[i][h] = fmaf(wv[i], ev[h], acc[i][h]);
        }
        __syncthreads();
    }
#pragma unroll
    for (int i = 0; i < 4; i++)
#pragma unroll
        for (int h = 0; h < 4; h++)
            g_ctx[(n * TT + i0 + ty * 4 + i) * HD + h0 + tx * 4 + h] = acc[i][h];
}

// ---------------- ff: g_ff[m][o] = [Q|ctx][m][:] . attn_ff_W[o][:] + b[o] --
__global__ __launch_bounds__(256) void ff_kernel(
    const float* __restrict__ W, const float* __restrict__ b)
{
    __shared__ float sa[64][36], swt[64][36];
    int bid = blockIdx.x;
    int m0 = (bid >> 3) * 64, o0 = (bid & 7) * 64;
    int tid = threadIdx.x, tx = tid & 15, ty = tid >> 4;
    float acc[4][4];
#pragma unroll
    for (int i = 0; i < 4; i++)
#pragma unroll
        for (int o = 0; o < 4; o++) acc[i][o] = 0.f;

    for (int st = 0; st < 32; ++st) {
        int k0 = st * 32;
        const float* A = (k0 < HD) ? g_Q : g_ctx;
        int koff = (k0 < HD) ? k0 : k0 - HD;
        for (int v = tid; v < 512; v += 256) {
            int r = v >> 3, c = (v & 7) * 4;
            *(float4*)&sa[r][c] = *(const float4*)(A + (m0 + r) * HD + koff + c);
            *(float4*)&swt[r][c] = *(const float4*)(W + (o0 + r) * (2 * HD) + k0 + c);
        }
        __syncthreads();
#pragma unroll
        for (int k = 0; k < 32; ++k) {
            float av[4], wv[4];
#pragma unroll
            for (int i = 0; i < 4; i++) av[i] = sa[ty * 4 + i][k];
#pragma unroll
            for (int o = 0; o < 4; o++) wv[o] = swt[tx * 4 + o][k];
#pragma unroll
            for (int i = 0; i < 4; i++)
#pragma unroll
                for (int o = 0; o < 4; o++)
                    acc[i][o] = fmaf(av[i], wv[o], acc[i][o]);
        }
        __syncthreads();
    }
#pragma unroll
    for (int i = 0; i < 4; i++)
#pragma unroll
        for (int o = 0; o < 4; o++)
            g_ff[(m0 + ty * 4 + i) * HD + o0 + tx * 4 + o] = acc[i][o] + b[o0 + tx * 4 + o];
}

// ---------------- fc: v_out[m][s] = ff[m][:] . fc_W[s][:] + fc_b[s] --------
__global__ __launch_bounds__(256) void fc_kernel(
    const float* __restrict__ W, const float* __restrict__ b,
    float* __restrict__ vout)
{
    __shared__ float sa[128][36], swt[64][36];
    int m0 = blockIdx.x * 128;
    int tid = threadIdx.x, tx = tid & 15, ty = tid >> 4;
    float acc[8][4];
#pragma unroll
    for (int i = 0; i < 8; i++)
#pragma unroll
        for (int s = 0; s < 4; s++) acc[i][s] = 0.f;

    for (int st = 0; st < 16; ++st) {
        int k0 = st * 32;
        for (int v = tid; v < 1024; v += 256) {
            int r = v >> 3, c = (v & 7) * 4;
            *(float4*)&sa[r][c] = *(const float4*)(g_ff + (m0 + r) * HD + k0 + c);
        }
        for (int v = tid; v < 512; v += 256) {
            int r = v >> 3, c = (v & 7) * 4;
            *(float4*)&swt[r][c] = *(const float4*)(W + r * HD + k0 + c);
        }
        __syncthreads();
#pragma unroll
        for (int k = 0; k < 32; ++k) {
            float av[8], wv[4];
#pragma unroll
            for (int i = 0; i < 8; i++) av[i] = sa[ty * 8 + i][k];
#pragma unroll
            for (int s = 0; s < 4; s++) wv[s] = swt[tx * 4 + s][k];
#pragma unroll
            for (int i = 0; i < 8; i++)
#pragma unroll
                for (int s = 0; s < 4; s++)
                    acc[i][s] = fmaf(av[i], wv[s], acc[i][s]);
        }
        __syncthreads();
    }
#pragma unroll
    for (int i = 0; i < 8; i++)
#pragma unroll
        for (int s = 0; s < 4; s++)
            vout[(m0 + ty * 8 + i) * SS + tx * 4 + s] = acc[i][s] + b[tx * 4 + s];
}

// ---------------- launch ----------------------------------------------------
extern "C" void kernel_launch(void* const* d_in, const int* in_sizes, int n_in,
                              void* d_out, int out_size)
{
    const float* x      = (const float*)d_in[0];
    const int*   target = (const int*)  d_in[1];
    const float* eWih   = (const float*)d_in[2];
    const float* eWhh   = (const float*)d_in[3];
    const float* ebih   = (const float*)d_in[4];
    const float* ebhh   = (const float*)d_in[5];
    const float* dWih   = (const float*)d_in[6];
    const float* dWhh   = (const float*)d_in[7];
    const float* dbih   = (const float*)d_in[8];
    const float* dbhh   = (const float*)d_in[9];
    const float* emb    = (const float*)d_in[10];
    const float* aW     = (const float*)d_in[11];
    const float* ab     = (const float*)d_in[12];
    const float* fW     = (const float*)d_in[13];
    const float* fb     = (const float*)d_in[14];

    float* out   = (float*)d_out;
    float* v_out = out;                       // (128,128,64)  = 1048576
    float* hN    = out + 1048576;             // (1,128,512)   = 65536
    float* allw  = out + 1048576 + 65536;     // (128,128,512) = 8388608

    init_enc_kernel<<<256, 256>>>();
    embproj_kernel<<<64, 256>>>(emb, dWih, dbih);
    enc_kernel<<<128, 256>>>(x, eWih, eWhh, ebih, ebhh);
    dec_kernel<<<128, 256>>>(target, dWhh, dbhh);
    copyh_kernel<<<256, 256>>>(hN);
    scores_kernel<<<2048, 256>>>(allw);
    softmax_kernel<<<2048, 256>>>(allw);
    ctx_kernel<<<2048, 256>>>(allw);
    ff_kernel<<<2048, 256>>>(aW, ab);
    fc_kernel<<<128, 256>>>(fW, fb, v_out);
}